// round 1
// baseline (speedup 1.0000x reference)
#include <cuda_runtime.h>
#include <cuda_bf16.h>
#include <math.h>
#include <stdint.h>

// ContrastiveHead: NT-Xent loss, B=4096, D=256, T=0.1.
// loss = mean_i [ 10 + log(sum_{j!=i} exp(10*s_ij - 10)) - 10*s_{i,partner(i)} ]
// where s = fn fn^T, fn = row-normalized concat(q,k). No sim materialization.

#define NROWS 8192
#define HALFN 4096
#define DIM   256
#define BM    128
#define KP    264          // padded K stride (elements) -> conflict-free ldmatrix
#define NSPLIT 4
#define NITER 16           // (8192/NSPLIT)/128 column tiles per block
#define SMEM_BYTES (2 * BM * KP * 2)

__device__ __nv_bfloat16 g_fbf[NROWS * DIM];   // normalized features, bf16 (4 MB)
__device__ float g_pos[NROWS];                 // fp32-exact positive similarity per row
__device__ float g_sumexp[NROWS];              // sum_{j!=i} exp(10*s_ij - 10)

// ---------------------------------------------------------------------------
// Kernel 1: normalize rows of concat(q,k), store bf16.
// One warp per row; each lane handles 8 contiguous floats.
// ---------------------------------------------------------------------------
__global__ void normalize_kernel(const float* __restrict__ q,
                                 const float* __restrict__ k) {
    int gw   = (blockIdx.x * blockDim.x + threadIdx.x) >> 5;
    int lane = threadIdx.x & 31;
    if (gw >= NROWS) return;
    const float* src = (gw < HALFN) ? (q + (size_t)gw * DIM)
                                    : (k + (size_t)(gw - HALFN) * DIM);
    const float4* s4 = (const float4*)src;
    float4 v0 = s4[lane * 2 + 0];
    float4 v1 = s4[lane * 2 + 1];
    float ss = v0.x*v0.x + v0.y*v0.y + v0.z*v0.z + v0.w*v0.w
             + v1.x*v1.x + v1.y*v1.y + v1.z*v1.z + v1.w*v1.w;
    #pragma unroll
    for (int o = 16; o; o >>= 1) ss += __shfl_xor_sync(0xffffffffu, ss, o);
    float scale = 1.0f / fmaxf(sqrtf(ss), 1e-12f);

    __nv_bfloat162 h0 = __floats2bfloat162_rn(v0.x * scale, v0.y * scale);
    __nv_bfloat162 h1 = __floats2bfloat162_rn(v0.z * scale, v0.w * scale);
    __nv_bfloat162 h2 = __floats2bfloat162_rn(v1.x * scale, v1.y * scale);
    __nv_bfloat162 h3 = __floats2bfloat162_rn(v1.z * scale, v1.w * scale);
    uint4 o4;
    o4.x = *(const uint32_t*)&h0;
    o4.y = *(const uint32_t*)&h1;
    o4.z = *(const uint32_t*)&h2;
    o4.w = *(const uint32_t*)&h3;
    *(uint4*)(g_fbf + (size_t)gw * DIM + lane * 8) = o4;
}

// ---------------------------------------------------------------------------
// Kernel 2: fp32-exact positives + zero the sum-exp accumulators.
// One warp per pair i: pos = dot(q_i,k_i)/(||q_i||*||k_i||).
// ---------------------------------------------------------------------------
__global__ void pos_kernel(const float* __restrict__ q,
                           const float* __restrict__ k) {
    int gt = blockIdx.x * blockDim.x + threadIdx.x;
    if (gt < NROWS) g_sumexp[gt] = 0.0f;
    int gw   = gt >> 5;
    int lane = gt & 31;
    if (gw >= HALFN) return;
    const float4* q4 = (const float4*)(q + (size_t)gw * DIM);
    const float4* k4 = (const float4*)(k + (size_t)gw * DIM);
    float4 a0 = q4[lane*2], a1 = q4[lane*2+1];
    float4 b0 = k4[lane*2], b1 = k4[lane*2+1];
    float sq = a0.x*a0.x + a0.y*a0.y + a0.z*a0.z + a0.w*a0.w
             + a1.x*a1.x + a1.y*a1.y + a1.z*a1.z + a1.w*a1.w;
    float sk = b0.x*b0.x + b0.y*b0.y + b0.z*b0.z + b0.w*b0.w
             + b1.x*b1.x + b1.y*b1.y + b1.z*b1.z + b1.w*b1.w;
    float dp = a0.x*b0.x + a0.y*b0.y + a0.z*b0.z + a0.w*b0.w
             + a1.x*b1.x + a1.y*b1.y + a1.z*b1.z + a1.w*b1.w;
    #pragma unroll
    for (int o = 16; o; o >>= 1) {
        sq += __shfl_xor_sync(0xffffffffu, sq, o);
        sk += __shfl_xor_sync(0xffffffffu, sk, o);
        dp += __shfl_xor_sync(0xffffffffu, dp, o);
    }
    if (lane == 0) {
        float p = dp / (fmaxf(sqrtf(sq), 1e-12f) * fmaxf(sqrtf(sk), 1e-12f));
        g_pos[gw]         = p;
        g_pos[gw + HALFN] = p;
    }
}

// ---------------------------------------------------------------------------
// HMMA helpers
// ---------------------------------------------------------------------------
__device__ __forceinline__ void ldsm_x4(uint32_t* r, const void* p) {
    uint32_t a = (uint32_t)__cvta_generic_to_shared(p);
    asm volatile("ldmatrix.sync.aligned.m8n8.x4.shared.b16 {%0,%1,%2,%3}, [%4];"
                 : "=r"(r[0]), "=r"(r[1]), "=r"(r[2]), "=r"(r[3]) : "r"(a));
}
__device__ __forceinline__ void ldsm_x2(uint32_t* r, const void* p) {
    uint32_t a = (uint32_t)__cvta_generic_to_shared(p);
    asm volatile("ldmatrix.sync.aligned.m8n8.x2.shared.b16 {%0,%1}, [%2];"
                 : "=r"(r[0]), "=r"(r[1]) : "r"(a));
}
__device__ __forceinline__ void mma16816(float* c, const uint32_t* a, const uint32_t* b) {
    asm volatile(
        "mma.sync.aligned.m16n8k16.row.col.f32.bf16.bf16.f32 "
        "{%0,%1,%2,%3}, {%4,%5,%6,%7}, {%8,%9}, {%0,%1,%2,%3};"
        : "+f"(c[0]), "+f"(c[1]), "+f"(c[2]), "+f"(c[3])
        : "r"(a[0]), "r"(a[1]), "r"(a[2]), "r"(a[3]), "r"(b[0]), "r"(b[1]));
}

// ---------------------------------------------------------------------------
// Kernel 3: fused GEMM (bf16 HMMA) + per-row sum of exp(10*s-10), diag masked.
// Grid (64, NSPLIT). Block = 256 threads = 8 warps in a 4(m) x 2(n) layout.
// Each warp: 2 m-tiles (m16) x 8 n-tiles (n8). K=256 fully resident in smem.
// ---------------------------------------------------------------------------
__global__ void __launch_bounds__(256, 1) sim_kernel() {
    extern __shared__ __nv_bfloat16 sm[];
    __nv_bfloat16* As = sm;
    __nv_bfloat16* Bs = sm + BM * KP;

    int tid = threadIdx.x;
    int lane = tid & 31;
    int w = tid >> 5;
    int wm = w >> 1;           // 0..3
    int wn = w & 1;            // 0..1
    int mBase = blockIdx.x * BM;
    int nSplitBase = blockIdx.y * (NITER * 128);

    // Load A tile (128 rows x 256 K), once per block.
    for (int idx = tid; idx < BM * (DIM / 8); idx += 256) {
        int r = idx >> 5, c = idx & 31;
        uint4 v = ((const uint4*)(g_fbf + (size_t)(mBase + r) * DIM))[c];
        *(uint4*)(As + r * KP + c * 8) = v;
    }

    float rowsum[4] = {0.f, 0.f, 0.f, 0.f};
    int g  = lane >> 2;
    int qd = (lane & 3) * 2;
    const float C10 = 14.426950408889634f;   // 10 * log2(e)

    int al = lane & 15;
    int acolo = (lane >> 4) * 8;
    int bl = lane & 15;
    int brow_off = bl & 7;
    int bcolo = ((bl >> 3) & 1) * 8;

    for (int it = 0; it < NITER; ++it) {
        __syncthreads();   // prior reads of Bs done (and As visible on iter 0)
        int nTileBase = nSplitBase + it * 128;
        for (int idx = tid; idx < 128 * (DIM / 8); idx += 256) {
            int r = idx >> 5, c = idx & 31;
            uint4 v = ((const uint4*)(g_fbf + (size_t)(nTileBase + r) * DIM))[c];
            *(uint4*)(Bs + r * KP + c * 8) = v;
        }
        __syncthreads();

        float cfr[2][8][4];
        #pragma unroll
        for (int mt = 0; mt < 2; ++mt)
            #pragma unroll
            for (int nt = 0; nt < 8; ++nt)
                #pragma unroll
                for (int e = 0; e < 4; ++e) cfr[mt][nt][e] = 0.f;

        #pragma unroll 4
        for (int kk = 0; kk < 16; ++kk) {
            int k0 = kk * 16;
            uint32_t afr[2][4], bfr[8][2];
            #pragma unroll
            for (int mt = 0; mt < 2; ++mt)
                ldsm_x4(afr[mt], As + (wm * 32 + mt * 16 + al) * KP + k0 + acolo);
            #pragma unroll
            for (int nt = 0; nt < 8; ++nt)
                ldsm_x2(bfr[nt], Bs + (wn * 64 + nt * 8 + brow_off) * KP + k0 + bcolo);
            #pragma unroll
            for (int mt = 0; mt < 2; ++mt)
                #pragma unroll
                for (int nt = 0; nt < 8; ++nt)
                    mma16816(cfr[mt][nt], afr[mt], bfr[nt]);
        }

        // Epilogue: exp(10*s - 10) with diagonal masked, accumulate per-row.
        #pragma unroll
        for (int mt = 0; mt < 2; ++mt) {
            int r0 = mBase + wm * 32 + mt * 16 + g;   // and r0+8
            #pragma unroll
            for (int nt = 0; nt < 8; ++nt) {
                int c0 = nTileBase + wn * 64 + nt * 8 + qd;
                float* cc = cfr[mt][nt];
                float e0 = (c0     != r0    ) ? exp2f((cc[0] - 1.f) * C10) : 0.f;
                float e1 = (c0 + 1 != r0    ) ? exp2f((cc[1] - 1.f) * C10) : 0.f;
                float e2 = (c0     != r0 + 8) ? exp2f((cc[2] - 1.f) * C10) : 0.f;
                float e3 = (c0 + 1 != r0 + 8) ? exp2f((cc[3] - 1.f) * C10) : 0.f;
                rowsum[mt * 2 + 0] += e0 + e1;
                rowsum[mt * 2 + 1] += e2 + e3;
            }
        }
    }

    // Reduce across the 4 lanes sharing each row, then atomically combine.
    #pragma unroll
    for (int j = 0; j < 4; ++j) {
        rowsum[j] += __shfl_xor_sync(0xffffffffu, rowsum[j], 1);
        rowsum[j] += __shfl_xor_sync(0xffffffffu, rowsum[j], 2);
    }
    if ((lane & 3) == 0) {
        #pragma unroll
        for (int mt = 0; mt < 2; ++mt) {
            int r0 = mBase + wm * 32 + mt * 16 + g;
            atomicAdd(&g_sumexp[r0],     rowsum[mt * 2 + 0]);
            atomicAdd(&g_sumexp[r0 + 8], rowsum[mt * 2 + 1]);
        }
    }
}

// ---------------------------------------------------------------------------
// Kernel 4: final reduction -> scalar loss.
// ---------------------------------------------------------------------------
__global__ void finalize_kernel(float* __restrict__ out) {
    __shared__ float sh[256];
    int tid = threadIdx.x;
    float acc = 0.f;
    for (int i = tid; i < NROWS; i += 256)
        acc += 10.f + logf(g_sumexp[i]) - 10.f * g_pos[i];
    sh[tid] = acc;
    __syncthreads();
    for (int s = 128; s; s >>= 1) {
        if (tid < s) sh[tid] += sh[tid + s];
        __syncthreads();
    }
    if (tid == 0) out[0] = sh[0] / (float)NROWS;
}

extern "C" void kernel_launch(void* const* d_in, const int* in_sizes, int n_in,
                              void* d_out, int out_size) {
    const float* q = (const float*)d_in[0];
    const float* k = (const float*)d_in[1];
    float* out = (float*)d_out;

    cudaFuncSetAttribute(sim_kernel, cudaFuncAttributeMaxDynamicSharedMemorySize,
                         SMEM_BYTES);

    normalize_kernel<<<NROWS / 8, 256>>>(q, k);
    pos_kernel<<<HALFN / 8, 256>>>(q, k);
    sim_kernel<<<dim3(64, NSPLIT), 256, SMEM_BYTES>>>();
    finalize_kernel<<<1, 256>>>(out);
}